// round 14
// baseline (speedup 1.0000x reference)
#include <cuda_runtime.h>
#include <math.h>
#include <stdint.h>

// Problem constants
constexpr int Lc    = 50;
constexpr int NSEQ  = 32 * 40;     // 1280 sequences
constexpr int NR    = NSEQ * Lc;   // 64000 (seq,time) rows
constexpr int H     = 128;
constexpr int G4    = 512;         // 4*H gates

// ---------------------------------------------------------------------------
// Device scratch
// ---------------------------------------------------------------------------
__device__ float g_X0[(size_t)NR * 64];
__device__ float g_Xa[(size_t)NR * 256];
__device__ float g_Xb[(size_t)NR * 256];
__device__ float g_xg[2][(size_t)NR * G4];   // t-major: [dir][t][seq][512]
__device__ float g_agg[(size_t)NSEQ * 768];
__device__ float g_t1[(size_t)NSEQ * 512];
__device__ float g_t2[(size_t)NSEQ * 512];

// ---------------------------------------------------------------------------
// helpers
// ---------------------------------------------------------------------------
__device__ __forceinline__ float2 ffma2(float2 a, float2 b, float2 c) {
    unsigned long long ud;
    asm("fma.rn.f32x2 %0, %1, %2, %3;"
        : "=l"(ud)
        : "l"(*(unsigned long long*)&a),
          "l"(*(unsigned long long*)&b),
          "l"(*(unsigned long long*)&c));
    float2 d; *(unsigned long long*)&d = ud; return d;
}
__device__ __forceinline__ float2 pack2(float lo, float hi) {
    float2 r; r.x = lo; r.y = hi; return r;
}
__device__ __forceinline__ float sigm_(float x) {
    return __fdividef(1.0f, 1.0f + __expf(-x));
}
__device__ __forceinline__ float tanh_(float x) {
    return __fdividef(2.0f, 1.0f + __expf(-2.0f * x)) - 1.0f;
}
__device__ __forceinline__ uint32_t f2tf(float x) {
    uint32_t r;
    asm("cvt.rna.tf32.f32 %0, %1;" : "=r"(r) : "f"(x));
    return r;
}
__device__ __forceinline__ void mma_tf32(float* d, const uint32_t* a,
                                         const uint32_t* b) {
    asm volatile(
        "mma.sync.aligned.m16n8k8.row.col.f32.tf32.tf32.f32 "
        "{%0,%1,%2,%3}, {%4,%5,%6,%7}, {%8,%9}, {%0,%1,%2,%3};\n"
        : "+f"(d[0]), "+f"(d[1]), "+f"(d[2]), "+f"(d[3])
        : "r"(a[0]), "r"(a[1]), "r"(a[2]), "r"(a[3]), "r"(b[0]), "r"(b[1]));
}
__device__ __forceinline__ uint32_t smem_u32(const void* p) {
    uint32_t a;
    asm("{ .reg .u64 t; cvta.to.shared.u64 t, %1; cvt.u32.u64 %0, t; }"
        : "=r"(a) : "l"(p));
    return a;
}

// ---------------------------------------------------------------------------
// Kernel 1: input projection
// ---------------------------------------------------------------------------
__global__ __launch_bounds__(256) void inproj_kernel(
    const float* __restrict__ imu, const float* __restrict__ Win,
    const float* __restrict__ bin)
{
    int idx = blockIdx.x * 256 + threadIdx.x;
    int row = idx >> 6;
    int jj  = idx & 63;
    int l   = row % Lc;
    const float* xr = imu + (size_t)row * 6;
    float t    = (float)l * (1.0f / 49.0f);
    float rate = 1.0f;
    float acc = bin[jj];
#pragma unroll
    for (int k = 0; k < 6; k++) acc = fmaf(xr[k], Win[k * 64 + jj], acc);
    acc = fmaf(t,    Win[6 * 64 + jj], acc);
    acc = fmaf(rate, Win[7 * 64 + jj], acc);
    g_X0[(size_t)row * 64 + jj] = fmaxf(acc, 0.0f);
}

// ---------------------------------------------------------------------------
// Kernel 2: tf32 tensor-core GEMM + bias.
// Block tile 128x256, BK=16, 8 warps (2x4) of 64x64 warp tiles, m16n8k8.
// THREE-stage smem ring, distance-2 LDG prefetch: LDG(t+2) has a full
// iteration to land before its STS at iter t+1 -> global latency hidden.
// permute: t-major output rows.
// ---------------------------------------------------------------------------
constexpr int APITCH = 132;                 // floats per (ks,c) A row
constexpr int BPITCH = 516;                 // floats per (ks,kp) B row
constexpr int ASZ = 2 * 8 * APITCH;         // floats per A stage
constexpr int BSZ = 2 * 4 * BPITCH;         // floats per B stage
constexpr int GEMM_SMEM = 3 * (ASZ + BSZ) * 4;   // 74,880 bytes

__device__ __forceinline__ int asI(int buf, int ks, int c, int q) {
    return ((buf * 2 + ks) * 8 + c) * APITCH + q;
}
__device__ __forceinline__ int bsI(int buf, int ks, int kp, int q) {
    return ((buf * 2 + ks) * 4 + kp) * BPITCH + q;
}

__global__ __launch_bounds__(256) void tf32_gemm(
    const float* __restrict__ A, const float* __restrict__ B,
    float* __restrict__ C,
    const float* __restrict__ bias1, const float* __restrict__ bias2,
    int M, int N, int K,
    long long sB, long long sC, long long sBias, int nbx, int permute)
{
    extern __shared__ uint32_t sm[];
    uint32_t* As = sm;               // [3][2][8][APITCH]
    uint32_t* Bs = sm + 3 * ASZ;     // [3][2][4][BPITCH]

    const int dir = blockIdx.x / nbx;
    const int nb  = blockIdx.x % nbx;
    const int mb  = blockIdx.y;
    B += (size_t)dir * sB;
    C += (size_t)dir * sC;
    const float* b1 = bias1 + (size_t)dir * sBias;
    const float* b2 = bias2 ? bias2 + (size_t)dir * sBias : nullptr;
    const bool hasB2 = (b2 != nullptr);

    const int tid  = threadIdx.x;
    const int warp = tid >> 5, lane = tid & 31;
    const int wR = warp >> 2, wC = warp & 3;     // 2 x 4 warps, 64x64 each
    const int g  = lane >> 2, tig = lane & 3;

    const float* Ab = A + (size_t)(mb * 128) * K;
    const float* Bb = B + nb * 256;

    // A loader: row = tid>>1 (0..127), ks = tid&1, two float4 (c0 = 0, 4)
    const int aRow = tid >> 1;
    const int aks  = tid & 1;
    const int aQ   = ((aRow >> 4) << 4) + ((aRow & 7) << 1) + ((aRow >> 3) & 1);
    // B loader: k = tid>>4 (0..15), four float4 across 256 cols
    const int bk   = tid >> 4;
    const int bks  = bk >> 3, br8 = bk & 7;
    const int bkp  = br8 & 3, bhalf = br8 >> 2;
    const int bn0  = (tid & 15) * 4;

    float acc[4][8][4];
#pragma unroll
    for (int mt = 0; mt < 4; mt++)
#pragma unroll
        for (int nt = 0; nt < 8; nt++)
#pragma unroll
            for (int q = 0; q < 4; q++) acc[mt][nt][q] = 0.0f;

    const int niter = K / 16;
    float4 av[2], bv[4];

    // prologue: tile 0 -> buf0 (via regs), tile 1 -> regs (held)
    {
#pragma unroll
        for (int j = 0; j < 2; j++)
            av[j] = *(const float4*)(Ab + (size_t)aRow * K + aks * 8 + j * 4);
#pragma unroll
        for (int i = 0; i < 4; i++)
            bv[i] = *(const float4*)(Bb + (size_t)bk * N + bn0 + i * 64);
#pragma unroll
        for (int j = 0; j < 2; j++) {
            uint32_t* d = &As[asI(0, aks, j * 4, aQ)];
            d[0] = f2tf(av[j].x); d[APITCH] = f2tf(av[j].y);
            d[2 * APITCH] = f2tf(av[j].z); d[3 * APITCH] = f2tf(av[j].w);
        }
#pragma unroll
        for (int i = 0; i < 4; i++) {
            int n0 = bn0 + i * 64;
            uint32_t* d = &Bs[bsI(0, bks, bkp, n0 * 2 + bhalf)];
            d[0] = f2tf(bv[i].x); d[2] = f2tf(bv[i].y);
            d[4] = f2tf(bv[i].z); d[6] = f2tf(bv[i].w);
        }
        // tile 1 into regs
#pragma unroll
        for (int j = 0; j < 2; j++)
            av[j] = *(const float4*)(Ab + (size_t)aRow * K + 16 + aks * 8 + j * 4);
#pragma unroll
        for (int i = 0; i < 4; i++)
            bv[i] = *(const float4*)(Bb + (size_t)(16 + bk) * N + bn0 + i * 64);
    }
    __syncthreads();

    for (int it = 0; it < niter; it++) {
        const int cur = it % 3;
        // STS tile it+1 (held in regs) into buf (it+1)%3
        if (it + 1 < niter) {
            const int nxt = (it + 1) % 3;
#pragma unroll
            for (int j = 0; j < 2; j++) {
                uint32_t* d = &As[asI(nxt, aks, j * 4, aQ)];
                d[0] = f2tf(av[j].x); d[APITCH] = f2tf(av[j].y);
                d[2 * APITCH] = f2tf(av[j].z); d[3 * APITCH] = f2tf(av[j].w);
            }
#pragma unroll
            for (int i = 0; i < 4; i++) {
                int n0 = bn0 + i * 64;
                uint32_t* d = &Bs[bsI(nxt, bks, bkp, n0 * 2 + bhalf)];
                d[0] = f2tf(bv[i].x); d[2] = f2tf(bv[i].y);
                d[4] = f2tf(bv[i].z); d[6] = f2tf(bv[i].w);
            }
        }
        // LDG tile it+2 into regs (a full iteration to land)
        if (it + 2 < niter) {
            int k0 = (it + 2) * 16;
#pragma unroll
            for (int j = 0; j < 2; j++)
                av[j] = *(const float4*)(Ab + (size_t)aRow * K + k0 + aks * 8 + j * 4);
#pragma unroll
            for (int i = 0; i < 4; i++)
                bv[i] = *(const float4*)(Bb + (size_t)(k0 + bk) * N + bn0 + i * 64);
        }
        __syncthreads();

#pragma unroll
        for (int ks = 0; ks < 2; ks++) {
            uint32_t af[4][4];
#pragma unroll
            for (int mt = 0; mt < 4; mt++) {
                int q = ((wR * 4 + mt) << 4) + (g << 1);
                uint2 u0 = *(const uint2*)&As[asI(cur, ks, tig, q)];
                uint2 u1 = *(const uint2*)&As[asI(cur, ks, tig + 4, q)];
                af[mt][0] = u0.x; af[mt][1] = u0.y;
                af[mt][2] = u1.x; af[mt][3] = u1.y;
            }
            uint32_t bf[8][2];
#pragma unroll
            for (int nt = 0; nt < 8; nt++) {
                int n = wC * 64 + nt * 8 + g;
                uint2 u = *(const uint2*)&Bs[bsI(cur, ks, tig, n * 2)];
                bf[nt][0] = u.x; bf[nt][1] = u.y;
            }
#pragma unroll
            for (int mt = 0; mt < 4; mt++)
#pragma unroll
                for (int nt = 0; nt < 8; nt++)
                    mma_tf32(acc[mt][nt], af[mt], bf[nt]);
        }
    }

    // epilogue
#pragma unroll
    for (int mt = 0; mt < 4; mt++) {
        int rowa = mb * 128 + wR * 64 + mt * 16 + g;
        int rowb = rowa + 8;
        size_t ra = permute ? ((size_t)(rowa % Lc) * NSEQ + rowa / Lc) : (size_t)rowa;
        size_t rb = permute ? ((size_t)(rowb % Lc) * NSEQ + rowb / Lc) : (size_t)rowb;
#pragma unroll
        for (int nt = 0; nt < 8; nt++) {
            int colg = nb * 256 + wC * 64 + nt * 8 + 2 * tig;
            float bx = b1[colg], by = b1[colg + 1];
            if (hasB2) { bx += b2[colg]; by += b2[colg + 1]; }
            float2 v0 = pack2(acc[mt][nt][0] + bx, acc[mt][nt][1] + by);
            float2 v1 = pack2(acc[mt][nt][2] + bx, acc[mt][nt][3] + by);
            *(float2*)(C + ra * N + colg) = v0;
            *(float2*)(C + rb * N + colg) = v1;
        }
    }
}

// ---------------------------------------------------------------------------
// Kernel 3: PERSISTENT BiLSTM layer — DSMEM push exchange (round-12 version).
// ---------------------------------------------------------------------------
#define BARRG(rgid) asm volatile("bar.sync %0, 64;" :: "r"(rgid) : "memory")

constexpr int RGSZ = 3 * 128 * 2;              // floats per rg slice
constexpr int HBUF = 8 * RGSZ;                 // floats per h buffer
constexpr int LSTM_SMEM = 128 * 64 * 16        // ws
                        + 2 * HBUF * 4         // double-buffered h
                        + 8 * 8;               // 8 mbarriers

__global__ __launch_bounds__(512) __cluster_dims__(2, 1, 1)
void lstm_layer(const float* __restrict__ Whh,
                const float* __restrict__ xgb,   // t-major [dir][t][seq][512]
                float* __restrict__ Xout)
{
    extern __shared__ float smem[];
    float4* ws  = (float4*)smem;                 // [128][64] gate quads
    float*  hsf = smem + 128 * 64 * 4;           // 2 x HBUF
    unsigned long long* mbar =
        (unsigned long long*)(hsf + 2 * HBUF);   // [8] per-rg mbarriers

    const int bx   = blockIdx.x;
    const int dir  = bx >> 6;
    const int jt   = bx & 1;                     // cluster rank
    const int rgI  = (bx >> 1) & 31;
    const int row0 = rgI * 40;
    const int tid  = threadIdx.x;
    const int warp = tid >> 5, lane = tid & 31;
    const int rg   = warp >> 1, jh = warp & 1;
    const int jcol = (jh << 5) + lane;           // 0..63
    const int col  = (jt << 6) + jcol;           // 0..127
    const int rbase = row0 + rg * 5;

    const float* W   = Whh + (size_t)dir * (H * G4);
    const float* xgd = xgb + (size_t)dir * NR * G4;

    if (tid < 8) {
        uint32_t mb = smem_u32(&mbar[tid]);
        asm volatile("mbarrier.init.shared.b64 [%0], %1;"
                     :: "r"(mb), "r"(64) : "memory");
    }

    for (int idx = tid; idx < 128 * 64; idx += 512) {
        int k = idx >> 6, j = idx & 63;
        const float* wk = W + (size_t)k * G4 + (jt << 6) + j;
        ws[idx] = make_float4(wk[0], wk[128], wk[256], wk[384]);
    }
    __syncthreads();
    asm volatile("barrier.cluster.arrive.aligned;" ::: "memory");
    asm volatile("barrier.cluster.wait.aligned;" ::: "memory");

    const uint32_t mb_l = smem_u32(&mbar[rg]);
    uint32_t mb_r;
    asm("mapa.shared::cluster.u32 %0, %1, %2;"
        : "=r"(mb_r) : "r"(mb_l), "r"(jt ^ 1));
    const uint32_t hs_l = smem_u32(hsf);
    uint32_t hs_r;
    asm("mapa.shared::cluster.u32 %0, %1, %2;"
        : "=r"(hs_r) : "r"(hs_l), "r"(jt ^ 1));

    float c[5];
#pragma unroll
    for (int r = 0; r < 5; r++) c[r] = 0.0f;

    for (int step = 0; step < Lc; step++) {
        const int tin = dir ? (Lc - 1 - step) : step;

        float2 acc2[4][2];
        float  accs[4];
        const float* xp = xgd + ((size_t)tin * NSEQ + rbase) * G4 + col;
#pragma unroll
        for (int p = 0; p < 2; p++) {
            const float* xa = xp + (size_t)(2 * p) * G4;
            const float* xb = xa + G4;
#pragma unroll
            for (int gi = 0; gi < 4; gi++)
                acc2[gi][p] = pack2(xa[gi * 128], xb[gi * 128]);
        }
        {
            const float* xa = xp + (size_t)4 * G4;
#pragma unroll
            for (int gi = 0; gi < 4; gi++) accs[gi] = xa[gi * 128];
        }

        if (step > 0) {
            {
                const uint32_t parity = (uint32_t)((step - 1) & 1);
                uint32_t done;
                do {
                    asm volatile(
                        "{\n\t.reg .pred p;\n\t"
                        "mbarrier.try_wait.parity.acquire.cluster.shared::cta.b64 "
                        "p, [%1], %2;\n\t"
                        "selp.b32 %0, 1, 0, p;\n\t}"
                        : "=r"(done) : "r"(mb_l), "r"(parity) : "memory");
                } while (!done);
            }

            const float*  hrow  = hsf + ((step + 1) & 1) * HBUF + rg * RGSZ;
            const float2* hrow2 = (const float2*)hrow;
#pragma unroll 8
            for (int k = 0; k < 128; k++) {
                float4 w4 = ws[(k << 6) + jcol];
                float2 ha = hrow2[k];
                float2 hb = hrow2[128 + k];
                float  hc = hrow[(256 + k) * 2];
                float2 w0 = pack2(w4.x, w4.x);
                float2 w1 = pack2(w4.y, w4.y);
                float2 w2 = pack2(w4.z, w4.z);
                float2 w3 = pack2(w4.w, w4.w);
                acc2[0][0] = ffma2(ha, w0, acc2[0][0]);
                acc2[1][0] = ffma2(ha, w1, acc2[1][0]);
                acc2[2][0] = ffma2(ha, w2, acc2[2][0]);
                acc2[3][0] = ffma2(ha, w3, acc2[3][0]);
                acc2[0][1] = ffma2(hb, w0, acc2[0][1]);
                acc2[1][1] = ffma2(hb, w1, acc2[1][1]);
                acc2[2][1] = ffma2(hb, w2, acc2[2][1]);
                acc2[3][1] = ffma2(hb, w3, acc2[3][1]);
                accs[0] = fmaf(hc, w4.x, accs[0]);
                accs[1] = fmaf(hc, w4.y, accs[1]);
                accs[2] = fmaf(hc, w4.z, accs[2]);
                accs[3] = fmaf(hc, w4.w, accs[3]);
            }
        }

        float hval[5];
#pragma unroll
        for (int p = 0; p < 2; p++) {
            float i0 = sigm_(acc2[0][p].x), i1 = sigm_(acc2[0][p].y);
            float f0 = sigm_(acc2[1][p].x), f1 = sigm_(acc2[1][p].y);
            float ga = tanh_(acc2[2][p].x), gb = tanh_(acc2[2][p].y);
            float o0 = sigm_(acc2[3][p].x), o1 = sigm_(acc2[3][p].y);
            float c0 = fmaf(f0, c[2 * p],     i0 * ga);
            float c1 = fmaf(f1, c[2 * p + 1], i1 * gb);
            c[2 * p] = c0; c[2 * p + 1] = c1;
            hval[2 * p]     = o0 * tanh_(c0);
            hval[2 * p + 1] = o1 * tanh_(c1);
        }
        {
            float ig = sigm_(accs[0]);
            float fg = sigm_(accs[1]);
            float gg = tanh_(accs[2]);
            float og = sigm_(accs[3]);
            float cn = fmaf(fg, c[4], ig * gg);
            c[4] = cn;
            hval[4] = og * tanh_(cn);
        }

        if (step < Lc - 1) {
            const int bofs = (step & 1) * HBUF + rg * RGSZ;
            float* hw = hsf + bofs;
            const uint32_t hwr = hs_r + (uint32_t)bofs * 4u;
#pragma unroll
            for (int r = 0; r < 5; r++) {
                const int idx = (((r >> 1) << 7) + col) * 2 + (r & 1);
                hw[idx] = hval[r];
                asm volatile("st.shared::cluster.f32 [%0], %1;"
                             :: "r"(hwr + (uint32_t)idx * 4u), "f"(hval[r])
                             : "memory");
            }
            BARRG(rg);
            asm volatile(
                "mbarrier.arrive.release.cluster.shared::cluster.b64 _, [%0];"
                :: "r"(mb_r) : "memory");
        }

#pragma unroll
        for (int r = 0; r < 5; r++)
            Xout[((size_t)(rbase + r) * Lc + tin) * 256 + dir * H + col] = hval[r];
    }

    asm volatile("barrier.cluster.arrive.aligned;" ::: "memory");
    asm volatile("barrier.cluster.wait.aligned;" ::: "memory");
}

// ---------------------------------------------------------------------------
// Kernel 4: aggregation
// ---------------------------------------------------------------------------
__global__ __launch_bounds__(256) void agg_kernel(const float* __restrict__ X)
{
    int n = blockIdx.x, f = threadIdx.x;
    const float* base = X + (size_t)n * Lc * 256 + f;
    float s = 0.0f, m = -1e30f;
#pragma unroll 5
    for (int l = 0; l < Lc; l++) {
        float v = base[(size_t)l * 256];
        s += v; m = fmaxf(m, v);
    }
    g_agg[(size_t)n * 768 + f]       = s * (1.0f / Lc);
    g_agg[(size_t)n * 768 + 256 + f] = m;
    g_agg[(size_t)n * 768 + 512 + f] = (f < H) ? base[(Lc - 1) * 256] : base[0];
}

// ---------------------------------------------------------------------------
// Kernel 5: LayerNorm(512) + ReLU
// ---------------------------------------------------------------------------
__global__ __launch_bounds__(256) void ln_relu(
    const float* __restrict__ x, float* __restrict__ y,
    const float* __restrict__ gam, const float* __restrict__ bet)
{
    int row = blockIdx.x, tid = threadIdx.x;
    const float* xr = x + (size_t)row * 512;
    float v0 = xr[tid], v1 = xr[tid + 256];
    float s = v0 + v1, q = v0 * v0 + v1 * v1;
    __shared__ float ss[8], sq[8];
#pragma unroll
    for (int o = 16; o > 0; o >>= 1) {
        s += __shfl_down_sync(~0u, s, o);
        q += __shfl_down_sync(~0u, q, o);
    }
    int w = tid >> 5;
    if ((tid & 31) == 0) { ss[w] = s; sq[w] = q; }
    __syncthreads();
    if (tid == 0) {
        float S = 0.0f, Q = 0.0f;
        for (int i = 0; i < 8; i++) { S += ss[i]; Q += sq[i]; }
        ss[0] = S; sq[0] = Q;
    }
    __syncthreads();
    float mu  = ss[0] * (1.0f / 512.0f);
    float var = sq[0] * (1.0f / 512.0f) - mu * mu;
    float rs  = rsqrtf(var + 1e-5f);
    y[(size_t)row * 512 + tid]       = fmaxf((v0 - mu) * rs * gam[tid]       + bet[tid],       0.0f);
    y[(size_t)row * 512 + tid + 256] = fmaxf((v1 - mu) * rs * gam[tid + 256] + bet[tid + 256], 0.0f);
}

// ---------------------------------------------------------------------------
// Host orchestration
// ---------------------------------------------------------------------------
extern "C" void kernel_launch(void* const* d_in, const int* in_sizes, int n_in,
                              void* d_out, int out_size)
{
    const float* imu   = (const float*)d_in[0];
    const float* W_in  = (const float*)d_in[1];
    const float* b_in  = (const float*)d_in[2];
    const float* Wih[3] = {(const float*)d_in[3],  (const float*)d_in[7],  (const float*)d_in[11]};
    const float* Whh[3] = {(const float*)d_in[4],  (const float*)d_in[8],  (const float*)d_in[12]};
    const float* bih[3] = {(const float*)d_in[5],  (const float*)d_in[9],  (const float*)d_in[13]};
    const float* bhh[3] = {(const float*)d_in[6],  (const float*)d_in[10], (const float*)d_in[14]};
    const float* Wout1 = (const float*)d_in[15];
    const float* bout1 = (const float*)d_in[16];
    const float* ln_g  = (const float*)d_in[17];
    const float* ln_b  = (const float*)d_in[18];
    const float* Wout2 = (const float*)d_in[19];
    const float* bout2 = (const float*)d_in[20];
    float* out = (float*)d_out;

    float *pX0, *pXa, *pXb, *pxg, *pagg, *pt1, *pt2;
    cudaGetSymbolAddress((void**)&pX0,  g_X0);
    cudaGetSymbolAddress((void**)&pXa,  g_Xa);
    cudaGetSymbolAddress((void**)&pXb,  g_Xb);
    cudaGetSymbolAddress((void**)&pxg,  g_xg);
    cudaGetSymbolAddress((void**)&pagg, g_agg);
    cudaGetSymbolAddress((void**)&pt1,  g_t1);
    cudaGetSymbolAddress((void**)&pt2,  g_t2);

    cudaFuncSetAttribute(lstm_layer,
                         cudaFuncAttributeMaxDynamicSharedMemorySize, LSTM_SMEM);
    cudaFuncSetAttribute(tf32_gemm,
                         cudaFuncAttributeMaxDynamicSharedMemorySize, GEMM_SMEM);

    inproj_kernel<<<(NR * 64) / 256, 256>>>(imu, W_in, b_in);

    float* Xin  = pX0;
    int    Kin  = 64;
    float* Xout = pXa;
    for (int layer = 0; layer < 3; layer++) {
        // xg = Xin @ Wih + (bih+bhh); N=512 per dir -> nbx=2; both dirs in grid.x
        tf32_gemm<<<dim3(4, NR / 128), 256, GEMM_SMEM>>>(
            Xin, Wih[layer], pxg, bih[layer], bhh[layer],
            NR, G4, Kin,
            (long long)Kin * G4, (long long)NR * G4, (long long)G4, 2, 1);
        lstm_layer<<<128, 512, LSTM_SMEM>>>(Whh[layer], pxg, Xout);
        Xin = Xout;
        Kin = 256;
        Xout = (Xin == pXa) ? pXb : pXa;
    }
    float* Xfinal = Xin;

    agg_kernel<<<NSEQ, 256>>>(Xfinal);
    tf32_gemm<<<dim3(2, NSEQ / 128), 256, GEMM_SMEM>>>(
        pagg, Wout1, pt1, bout1, nullptr, NSEQ, 512, 768, 0, 0, 0, 2, 0);
    ln_relu<<<NSEQ, 256>>>(pt1, pt2, ln_g, ln_b);
    tf32_gemm<<<dim3(1, NSEQ / 128), 256, GEMM_SMEM>>>(
        pt2, Wout2, out, bout2, nullptr, NSEQ, 256, 512, 0, 0, 0, 1, 0);
}